// round 13
// baseline (speedup 1.0000x reference)
#include <cuda_runtime.h>
#include <cuda_fp16.h>
#include <math_constants.h>
#include <cstdint>

#define NN 500000
#define DD 256
#define CC 128
#define SSEG 2048

#define BM 128
#define BN 128
#define BK 32
#define PAW 20    // A fp16-word pitch: LDSM 8-row phases hit all 32 banks
#define PBW 136   // B word pitch: banks (tig*8+gid)%32 all distinct

// smem word offsets (19200 words = 76800 B; 2 CTAs/SM)
#define SAH_OFF(s)  ((s) * 2560)            // A fp16 words 128*20, 2 stages
#define SBH_OFF(s)  (10240 + (s) * 2176)    // B hi: 16*136
#define SBL_OFF(s)  (14592 + (s) * 2176)    // B lo
#define BIAS_OFF    18944
#define SMEM_BYTES  (19200 * 4)

// h stored as single fp16x2 words [m][kp]: 256 MB.
__device__ uint32_t g_h16[(long long)NN * 128];
// pre-split weights (fp16 hi/lo), word layout [kp][n]
__device__ uint32_t g_w1hi[128 * 256], g_w1lo[128 * 256];
__device__ uint32_t g_w2hi[128 * 128], g_w2lo[128 * 128];

#define MMA16816F16(d, a, b)                                                  \
    asm volatile(                                                             \
        "mma.sync.aligned.m16n8k16.row.col.f32.f16.f16.f32 "                  \
        "{%0,%1,%2,%3}, {%4,%5,%6,%7}, {%8,%9}, {%0,%1,%2,%3};"               \
        : "+f"((d)[0]), "+f"((d)[1]), "+f"((d)[2]), "+f"((d)[3])              \
        : "r"((a)[0]), "r"((a)[1]), "r"((a)[2]), "r"((a)[3]),                 \
          "r"((b)[0]), "r"((b)[1]))

#define LDSM4(r, addr)                                                        \
    asm volatile("ldmatrix.sync.aligned.m8n8.x4.shared.b16 {%0,%1,%2,%3}, [%4];" \
        : "=r"((r)[0]), "=r"((r)[1]), "=r"((r)[2]), "=r"((r)[3]) : "r"(addr))

__device__ __forceinline__ uint32_t pack1h(float x, float y) {
    __half2 h = __floats2half2_rn(x, y);
    return *reinterpret_cast<uint32_t*>(&h);
}
__device__ __forceinline__ void pack2h(float x, float y, uint32_t& hi, uint32_t& lo) {
    __half2 h = __floats2half2_rn(x, y);
    hi = *reinterpret_cast<uint32_t*>(&h);
    float rx = x - __low2float(h);
    float ry = y - __high2float(h);
    __half2 l = __floats2half2_rn(rx, ry);
    lo = *reinterpret_cast<uint32_t*>(&l);
}

__device__ __forceinline__ void cpa16(uint32_t dst, const void* src, int srcsz) {
    asm volatile("cp.async.cg.shared.global [%0], [%1], 16, %2;"
                 :: "r"(dst), "l"(src), "r"(srcsz));
}
#define CP_COMMIT()  asm volatile("cp.async.commit_group;" ::: "memory")
#define CP_WAIT0()   asm volatile("cp.async.wait_group 0;" ::: "memory")

// ===========================================================================
// Weight pre-split: W[k][n] fp32 -> fp16 hi/lo words [kp][n]
// ===========================================================================
__global__ __launch_bounds__(256) void convert_w(
    const float* __restrict__ W1, const float* __restrict__ W2)
{
    int idx = blockIdx.x * 256 + threadIdx.x;
    if (idx < 128 * 256) {
        int kp = idx >> 8, n = idx & 255;
        uint32_t hi, lo;
        pack2h(W1[(2 * kp) * 256 + n], W1[(2 * kp + 1) * 256 + n], hi, lo);
        g_w1hi[idx] = hi; g_w1lo[idx] = lo;
    } else {
        int j = idx - 128 * 256;
        if (j < 128 * 128) {
            int kp = j >> 7, n = j & 127;
            uint32_t hi, lo;
            pack2h(W2[(2 * kp) * 128 + n], W2[(2 * kp + 1) * 128 + n], hi, lo);
            g_w2hi[j] = hi; g_w2lo[j] = lo;
        }
    }
}

// ===========================================================================
// HMMA fp16 GEMM, A fragments via ldmatrix.
// ASTS:  A staged LDG fp32 -> cvt -> STS fp16 (gemm1) vs cp.async fp16 (gemm2)
// WH16:  write packed fp16 words (h) vs fp32 (logits)
// BSPLIT: B = hi+lo 2-product vs hi-only single product
// CTA 128x128, 8 warps (2m x 4n), warp tile 64x32, BK=32, 2-stage.
// ===========================================================================
template <int ASTS, int WH16, int BSPLIT>
__global__ __launch_bounds__(256, 2)
void gemm_hmma(const float* __restrict__ A32,
               const uint32_t* __restrict__ A16,
               const uint32_t* __restrict__ Bhi, const uint32_t* __restrict__ Blo,
               const float* __restrict__ bias,
               float* __restrict__ Cout, uint32_t* __restrict__ C16,
               int M, int Nfull, int relu)
{
    extern __shared__ float smem[];
    uint32_t* smw = reinterpret_cast<uint32_t*>(smem);
    const uint32_t smem32 = (uint32_t)__cvta_generic_to_shared(smem);

    const int tid  = threadIdx.x;
    const int lane = tid & 31;
    const int wid  = tid >> 5;
    const int wm   = wid & 1;
    const int wn   = wid >> 1;
    const int gid  = lane >> 2;
    const int tig  = lane & 3;
    const int m0   = blockIdx.x * BM;
    const int n0   = blockIdx.y * BN;

    if (tid < BN) smem[BIAS_OFF + tid] = bias[n0 + tid];

    float acc[4][4][4];
#pragma unroll
    for (int mt = 0; mt < 4; mt++)
#pragma unroll
        for (int nt = 0; nt < 4; nt++)
#pragma unroll
            for (int i = 0; i < 4; i++) acc[mt][nt][i] = 0.f;

    // staging maps
    const int srow = tid & 127;    // ASTS: one row per thread
    const int sseg = tid >> 7;     // 0/1 -> k half

    auto ldg_A = [&](int c, float4* ra) {
        int grow = m0 + srow;
        const float* src = &A32[(size_t)(grow < M ? grow : 0) * DD + c * BK + sseg * 16];
#pragma unroll
        for (int i = 0; i < 4; i++)
            ra[i] = *reinterpret_cast<const float4*>(src + i * 4);
    };
    auto sts_A = [&](int stg, const float4* ra) {
        int wadr = SAH_OFF(stg) + srow * PAW + sseg * 8;
        uint4 u0, u1;
        u0.x = pack1h(ra[0].x, ra[0].y);  u0.y = pack1h(ra[0].z, ra[0].w);
        u0.z = pack1h(ra[1].x, ra[1].y);  u0.w = pack1h(ra[1].z, ra[1].w);
        u1.x = pack1h(ra[2].x, ra[2].y);  u1.y = pack1h(ra[2].z, ra[2].w);
        u1.z = pack1h(ra[3].x, ra[3].y);  u1.w = pack1h(ra[3].z, ra[3].w);
        *reinterpret_cast<uint4*>(&smw[wadr])     = u0;
        *reinterpret_cast<uint4*>(&smw[wadr + 4]) = u1;
    };
    auto issue_A16 = [&](int c, int stg) {
#pragma unroll
        for (int l = 0; l < 2; l++) {
            int o = tid + 256 * l;
            int row = o >> 2, seg = o & 3;
            int grow = m0 + row;
            int ok = (grow < M);
            cpa16(smem32 + (uint32_t)(SAH_OFF(stg) + row * PAW + seg * 4) * 4u,
                  &A16[(size_t)(ok ? grow : 0) * 128 + c * 16 + seg * 4], ok ? 16 : 0);
        }
    };
    auto issue_B = [&](int c, int stg) {
#pragma unroll
        for (int l = 0; l < 2; l++) {
            int o = tid + 256 * l;
            int row = o >> 5, seg = o & 31;
            cpa16(smem32 + (uint32_t)(SBH_OFF(stg) + row * PBW + seg * 4) * 4u,
                  &Bhi[(size_t)(c * 16 + row) * Nfull + n0 + seg * 4], 16);
            if (BSPLIT)
                cpa16(smem32 + (uint32_t)(SBL_OFF(stg) + row * PBW + seg * 4) * 4u,
                      &Blo[(size_t)(c * 16 + row) * Nfull + n0 + seg * 4], 16);
        }
        CP_COMMIT();
    };

    // per-lane LDSM base (words, stage-relative)
    const int abase_rel = (wm * 64 + (lane & 15)) * PAW + (lane >> 4) * 4;

    float4 ra[4];
    if (ASTS) {
        ldg_A(0, ra);
        issue_B(0, 0);
    } else {
        issue_A16(0, 0);
        issue_B(0, 0);
    }

#pragma unroll 1
    for (int c = 0; c < 8; c++) {
        const int stg = c & 1;
        CP_WAIT0();
        __syncthreads();

        if (ASTS) {
            sts_A(stg, ra);
            __syncthreads();
            if (c < 7) {
                issue_B(c + 1, stg ^ 1);
                ldg_A(c + 1, ra);
            }
        } else {
            if (c < 7) {
                issue_A16(c + 1, stg ^ 1);
                issue_B(c + 1, stg ^ 1);
            }
        }

        const uint32_t abase = smem32 + (uint32_t)(SAH_OFF(stg) + abase_rel) * 4u;

#pragma unroll
        for (int s = 0; s < 2; s++) {
            // ---- B fragments (direct words) ----
            uint32_t bfh[4][2], bfl[4][2];
            const int kpb = 8 * s + tig;
#pragma unroll
            for (int nt = 0; nt < 4; nt++) {
                int ncol = wn * 32 + nt * 8 + gid;
                bfh[nt][0] = smw[SBH_OFF(stg) + (kpb    ) * PBW + ncol];
                bfh[nt][1] = smw[SBH_OFF(stg) + (kpb + 4) * PBW + ncol];
                if (BSPLIT) {
                    bfl[nt][0] = smw[SBL_OFF(stg) + (kpb    ) * PBW + ncol];
                    bfl[nt][1] = smw[SBL_OFF(stg) + (kpb + 4) * PBW + ncol];
                }
            }
            // ---- A fragments via ldmatrix.x4 (one per mt) ----
            uint32_t af[4][4];
#pragma unroll
            for (int mt = 0; mt < 4; mt++)
                LDSM4(af[mt], abase + (uint32_t)(mt * 16 * PAW + s * 8) * 4u);

#pragma unroll
            for (int mt = 0; mt < 4; mt++)
#pragma unroll
                for (int nt = 0; nt < 4; nt++)
                    MMA16816F16(acc[mt][nt], af[mt], bfh[nt]);
            if (BSPLIT) {
#pragma unroll
                for (int mt = 0; mt < 4; mt++)
#pragma unroll
                    for (int nt = 0; nt < 4; nt++)
                        MMA16816F16(acc[mt][nt], af[mt], bfl[nt]);
            }
        }
    }

    // ---- epilogue ----
    const float* sbias = smem + BIAS_OFF;
#pragma unroll
    for (int mt = 0; mt < 4; mt++) {
        int r0 = m0 + wm * 64 + mt * 16 + gid;
#pragma unroll
        for (int nt = 0; nt < 4; nt++) {
            int col = wn * 32 + nt * 8 + 2 * tig;
            float bv0 = sbias[col], bv1 = sbias[col + 1];
            float x0 = acc[mt][nt][0] + bv0;
            float x1 = acc[mt][nt][1] + bv1;
            float x2 = acc[mt][nt][2] + bv0;
            float x3 = acc[mt][nt][3] + bv1;
            if (relu) {
                x0 = fmaxf(x0, 0.f); x1 = fmaxf(x1, 0.f);
                x2 = fmaxf(x2, 0.f); x3 = fmaxf(x3, 0.f);
            }
            if (WH16) {
                int wcol = (n0 + col) >> 1;
                if (r0 < M)
                    C16[(size_t)r0 * 128 + wcol] = pack1h(x0, x1);
                if (r0 + 8 < M)
                    C16[(size_t)(r0 + 8) * 128 + wcol] = pack1h(x2, x3);
            } else {
                if (r0 < M)
                    *reinterpret_cast<float2*>(&Cout[(size_t)r0 * Nfull + n0 + col]) =
                        make_float2(x0, x1);
                if (r0 + 8 < M)
                    *reinterpret_cast<float2*>(&Cout[(size_t)(r0 + 8) * Nfull + n0 + col]) =
                        make_float2(x2, x3);
            }
        }
    }
}

// ===========================================================================
// Segment softmax: 256 threads, 8 rows in flight (q = tid/32), float4 cols.
// ===========================================================================
__device__ __forceinline__ int lower_bound_i32(const int* __restrict__ a,
                                               int n, int key)
{
    int lo = 0, hi = n;
    while (lo < hi) {
        int mid = (lo + hi) >> 1;
        if (a[mid] < key) lo = mid + 1; else hi = mid;
    }
    return lo;
}

__device__ __forceinline__ void upd(float& m, float& s, float x) {
    if (x > m) { s = s * __expf(m - x) + 1.f; m = x; }
    else       { s += __expf(x - m); }
}

__global__ __launch_bounds__(256) void seg_softmax(
    const float* __restrict__ logits,
    const int* __restrict__ batch,
    float* __restrict__ probs)
{
    __shared__ float sm_m[8 * 128];
    __shared__ float sm_s[8 * 128];

    const int s   = blockIdx.x;
    const int lo  = lower_bound_i32(batch, NN, s);
    const int hi  = lower_bound_i32(batch, NN, s + 1);
    const int q   = threadIdx.x >> 5;
    const int cb  = (threadIdx.x & 31) * 4;

    float m[4] = {-CUDART_INF_F, -CUDART_INF_F, -CUDART_INF_F, -CUDART_INF_F};
    float sum[4] = {0.f, 0.f, 0.f, 0.f};

    for (int r = lo + q; r < hi; r += 8) {
        float4 v = *reinterpret_cast<const float4*>(&logits[(size_t)r * CC + cb]);
        upd(m[0], sum[0], v.x);
        upd(m[1], sum[1], v.y);
        upd(m[2], sum[2], v.z);
        upd(m[3], sum[3], v.w);
    }
#pragma unroll
    for (int j = 0; j < 4; j++) {
        sm_m[q * 128 + cb + j] = m[j];
        sm_s[q * 128 + cb + j] = sum[j];
    }
    __syncthreads();

    if (threadIdx.x < 128) {
        const int c = threadIdx.x;
        float M = -CUDART_INF_F, S = 0.f;
#pragma unroll
        for (int qq = 0; qq < 8; qq++) {
            float mq = sm_m[qq * 128 + c], sq = sm_s[qq * 128 + c];
            if (sq > 0.f) {
                float nm = fmaxf(M, mq);
                S = S * __expf(M - nm) + sq * __expf(mq - nm);
                M = nm;
            }
        }
        sm_m[c] = M;
        sm_s[c] = (S > 0.f) ? (1.f / S) : 0.f;
    }
    __syncthreads();

    float mm[4], ii[4];
#pragma unroll
    for (int j = 0; j < 4; j++) { mm[j] = sm_m[cb + j]; ii[j] = sm_s[cb + j]; }

    for (int r = lo + q; r < hi; r += 8) {
        float4 v = *reinterpret_cast<const float4*>(&logits[(size_t)r * CC + cb]);
        float4 o;
        o.x = __expf(v.x - mm[0]) * ii[0];
        o.y = __expf(v.y - mm[1]) * ii[1];
        o.z = __expf(v.z - mm[2]) * ii[2];
        o.w = __expf(v.w - mm[3]) * ii[3];
        *reinterpret_cast<float4*>(&probs[(size_t)r * CC + cb]) = o;
    }
}

// ===========================================================================
// Launch
// ===========================================================================
extern "C" void kernel_launch(void* const* d_in, const int* in_sizes, int n_in,
                              void* d_out, int out_size)
{
    const float* H  = nullptr;
    const int*   batch = nullptr;
    const float* W1 = nullptr;
    const float* b1 = nullptr;
    const float* W2 = nullptr;
    const float* b2 = nullptr;

    for (int i = 0; i < n_in; i++) {
        switch (in_sizes[i]) {
            case 128000000: H     = (const float*)d_in[i]; break;
            case 500000:    batch = (const int*)d_in[i];   break;
            case 65536:     W1    = (const float*)d_in[i]; break;
            case 256:       b1    = (const float*)d_in[i]; break;
            case 32768:     W2    = (const float*)d_in[i]; break;
            case 128:       b2    = (const float*)d_in[i]; break;
            default: break;
        }
    }

    float* out    = (float*)d_out;
    float* logits = out;
    float* probs  = out + (size_t)NN * CC;

    void *h16, *w1hi, *w1lo, *w2hi, *w2lo;
    cudaGetSymbolAddress(&h16, g_h16);
    cudaGetSymbolAddress(&w1hi, g_w1hi);
    cudaGetSymbolAddress(&w1lo, g_w1lo);
    cudaGetSymbolAddress(&w2hi, g_w2hi);
    cudaGetSymbolAddress(&w2lo, g_w2lo);

    cudaFuncSetAttribute(gemm_hmma<1, 1, 0>,
                         cudaFuncAttributeMaxDynamicSharedMemorySize, SMEM_BYTES);
    cudaFuncSetAttribute(gemm_hmma<0, 0, 1>,
                         cudaFuncAttributeMaxDynamicSharedMemorySize, SMEM_BYTES);

    convert_w<<<192, 256>>>(W1, W2);

    const int mblocks = (NN + BM - 1) / BM;    // 3907

    // Layer 1: h = relu(H @ W1 + b1), single product (W1 hi), h -> fp16 words
    dim3 g1(mblocks, DD / BN);                 // 3907 x 2
    gemm_hmma<1, 1, 0><<<g1, 256, SMEM_BYTES>>>(
        H, nullptr, (const uint32_t*)w1hi, nullptr,
        b1, nullptr, (uint32_t*)h16, NN, DD, 1);

    // Layer 2: logits = h @ W2 + b2, 2-product (W2 split), fp32 out
    dim3 g2(mblocks, CC / BN);                 // 3907 x 1
    gemm_hmma<0, 0, 1><<<g2, 256, SMEM_BYTES>>>(
        nullptr, (const uint32_t*)h16, (const uint32_t*)w2hi, (const uint32_t*)w2lo,
        b2, logits, nullptr, NN, CC, 0);

    // Segment softmax -> probs
    seg_softmax<<<SSEG, 256>>>(logits, batch, probs);
}

// round 14
// speedup vs baseline: 1.2447x; 1.2447x over previous
#include <cuda_runtime.h>
#include <cuda_fp16.h>
#include <math_constants.h>
#include <cstdint>

#define NN 500000
#define DD 256
#define CC 128
#define SSEG 2048

#define BM 128
#define BN 128
#define BK 64
#define NCHUNK (DD / BK)     // 4
#define PAW 36    // A fp16-word pitch (32 + 4 pad): LDSM phases hit all banks
#define PBW 136   // B word pitch: frag banks (tig*8+gid)%32 all distinct

// smem word offsets (26880 words = 107520 B; 2 CTAs/SM)
#define SAH_OFF(s)  ((s) * 4608)            // A fp16 words 128*36, 2 stages
#define SBH_OFF(s)  (9216 + (s) * 4352)     // B hi: 32*136
#define SBL_OFF(s)  (17920 + (s) * 4352)    // B lo
#define BIAS_OFF    26624
#define SMEM_BYTES  (26880 * 4)

// H pre-converted to fp16x2 words [m][kp]: 256 MB.
__device__ uint32_t g_a16[(long long)NN * 128];
// h stored as fp16x2 words [m][kp]: 256 MB.
__device__ uint32_t g_h16[(long long)NN * 128];
// pre-split weights (fp16 hi/lo), word layout [kp][n]
__device__ uint32_t g_w1hi[128 * 256], g_w1lo[128 * 256];
__device__ uint32_t g_w2hi[128 * 128], g_w2lo[128 * 128];

#define MMA16816F16(d, a, b)                                                  \
    asm volatile(                                                             \
        "mma.sync.aligned.m16n8k16.row.col.f32.f16.f16.f32 "                  \
        "{%0,%1,%2,%3}, {%4,%5,%6,%7}, {%8,%9}, {%0,%1,%2,%3};"               \
        : "+f"((d)[0]), "+f"((d)[1]), "+f"((d)[2]), "+f"((d)[3])              \
        : "r"((a)[0]), "r"((a)[1]), "r"((a)[2]), "r"((a)[3]),                 \
          "r"((b)[0]), "r"((b)[1]))

#define LDSM4(r, addr)                                                        \
    asm volatile("ldmatrix.sync.aligned.m8n8.x4.shared.b16 {%0,%1,%2,%3}, [%4];" \
        : "=r"((r)[0]), "=r"((r)[1]), "=r"((r)[2]), "=r"((r)[3]) : "r"(addr))

__device__ __forceinline__ uint32_t pack1h(float x, float y) {
    __half2 h = __floats2half2_rn(x, y);
    return *reinterpret_cast<uint32_t*>(&h);
}
__device__ __forceinline__ void pack2h(float x, float y, uint32_t& hi, uint32_t& lo) {
    __half2 h = __floats2half2_rn(x, y);
    hi = *reinterpret_cast<uint32_t*>(&h);
    float rx = x - __low2float(h);
    float ry = y - __high2float(h);
    __half2 l = __floats2half2_rn(rx, ry);
    lo = *reinterpret_cast<uint32_t*>(&l);
}

__device__ __forceinline__ void cpa16(uint32_t dst, const void* src, int srcsz) {
    asm volatile("cp.async.cg.shared.global [%0], [%1], 16, %2;"
                 :: "r"(dst), "l"(src), "r"(srcsz));
}
#define CP_COMMIT()  asm volatile("cp.async.commit_group;" ::: "memory")
#define CP_WAIT0()   asm volatile("cp.async.wait_group 0;" ::: "memory")

// ===========================================================================
// H pre-conversion: fp32 -> fp16x2 words. 8 floats / thread.
// ===========================================================================
__global__ __launch_bounds__(256) void convert_h(
    const float* __restrict__ H, uint32_t* __restrict__ A16)
{
    size_t i = (size_t)blockIdx.x * 256 + threadIdx.x;   // < 16,000,000
    const float4* src = reinterpret_cast<const float4*>(H);
    float4 a = src[2 * i], b = src[2 * i + 1];
    uint4 o;
    o.x = pack1h(a.x, a.y);  o.y = pack1h(a.z, a.w);
    o.z = pack1h(b.x, b.y);  o.w = pack1h(b.z, b.w);
    reinterpret_cast<uint4*>(A16)[i] = o;
}

// ===========================================================================
// Weight pre-split: W[k][n] fp32 -> fp16 hi/lo words [kp][n]
// ===========================================================================
__global__ __launch_bounds__(256) void convert_w(
    const float* __restrict__ W1, const float* __restrict__ W2)
{
    int idx = blockIdx.x * 256 + threadIdx.x;
    if (idx < 128 * 256) {
        int kp = idx >> 8, n = idx & 255;
        uint32_t hi, lo;
        pack2h(W1[(2 * kp) * 256 + n], W1[(2 * kp + 1) * 256 + n], hi, lo);
        g_w1hi[idx] = hi; g_w1lo[idx] = lo;
    } else {
        int j = idx - 128 * 256;
        if (j < 128 * 128) {
            int kp = j >> 7, n = j & 127;
            uint32_t hi, lo;
            pack2h(W2[(2 * kp) * 128 + n], W2[(2 * kp + 1) * 128 + n], hi, lo);
            g_w2hi[j] = hi; g_w2lo[j] = lo;
        }
    }
}

// ===========================================================================
// HMMA fp16 GEMM: A fp16 words via cp.async + ldmatrix. BK=64, 2-stage.
// WH16:  write packed fp16 words (h) vs fp32 (logits)
// BSPLIT: B = hi+lo 2-product vs hi-only single product
// CTA 128x128, 8 warps (2m x 4n), warp tile 64x32.
// ===========================================================================
template <int WH16, int BSPLIT>
__global__ __launch_bounds__(256, 2)
void gemm_hmma(const uint32_t* __restrict__ A16,
               const uint32_t* __restrict__ Bhi, const uint32_t* __restrict__ Blo,
               const float* __restrict__ bias,
               float* __restrict__ Cout, uint32_t* __restrict__ C16,
               int M, int Nfull, int relu)
{
    extern __shared__ float smem[];
    uint32_t* smw = reinterpret_cast<uint32_t*>(smem);
    const uint32_t smem32 = (uint32_t)__cvta_generic_to_shared(smem);

    const int tid  = threadIdx.x;
    const int lane = tid & 31;
    const int wid  = tid >> 5;
    const int wm   = wid & 1;
    const int wn   = wid >> 1;
    const int gid  = lane >> 2;
    const int tig  = lane & 3;
    const int m0   = blockIdx.x * BM;
    const int n0   = blockIdx.y * BN;

    if (tid < BN) smem[BIAS_OFF + tid] = bias[n0 + tid];

    float acc[4][4][4];
#pragma unroll
    for (int mt = 0; mt < 4; mt++)
#pragma unroll
        for (int nt = 0; nt < 4; nt++)
#pragma unroll
            for (int i = 0; i < 4; i++) acc[mt][nt][i] = 0.f;

    auto issue_chunk = [&](int c, int stg) {
        // A: 128 rows x 32 words per chunk -> 1024 cpa16 / 256 thr = 4 each
#pragma unroll
        for (int l = 0; l < 4; l++) {
            int o = tid + 256 * l;
            int row = o >> 3, seg = o & 7;
            int grow = m0 + row;
            int ok = (grow < M);
            cpa16(smem32 + (uint32_t)(SAH_OFF(stg) + row * PAW + seg * 4) * 4u,
                  &A16[(size_t)(ok ? grow : 0) * 128 + c * 32 + seg * 4], ok ? 16 : 0);
        }
        // B: 32 rows x 128 cols words -> 1024 cpa16 / 256 thr = 4 each (x2 if split)
#pragma unroll
        for (int l = 0; l < 4; l++) {
            int o = tid + 256 * l;
            int row = o >> 5, seg = o & 31;
            cpa16(smem32 + (uint32_t)(SBH_OFF(stg) + row * PBW + seg * 4) * 4u,
                  &Bhi[(size_t)(c * 32 + row) * Nfull + n0 + seg * 4], 16);
            if (BSPLIT)
                cpa16(smem32 + (uint32_t)(SBL_OFF(stg) + row * PBW + seg * 4) * 4u,
                      &Blo[(size_t)(c * 32 + row) * Nfull + n0 + seg * 4], 16);
        }
        CP_COMMIT();
    };

    // per-lane LDSM base (words, stage-relative)
    const int abase_rel = (wm * 64 + (lane & 15)) * PAW + (lane >> 4) * 4;

    issue_chunk(0, 0);

#pragma unroll 1
    for (int c = 0; c < NCHUNK; c++) {
        const int stg = c & 1;
        CP_WAIT0();
        __syncthreads();
        if (c < NCHUNK - 1) issue_chunk(c + 1, stg ^ 1);

        const uint32_t abase = smem32 + (uint32_t)(SAH_OFF(stg) + abase_rel) * 4u;

#pragma unroll
        for (int s = 0; s < 4; s++) {             // 4 x k16 per chunk
            // ---- B fragments (direct words) ----
            uint32_t bfh[4][2], bfl[4][2];
            const int kpb = 8 * s + tig;
#pragma unroll
            for (int nt = 0; nt < 4; nt++) {
                int ncol = wn * 32 + nt * 8 + gid;
                bfh[nt][0] = smw[SBH_OFF(stg) + (kpb    ) * PBW + ncol];
                bfh[nt][1] = smw[SBH_OFF(stg) + (kpb + 4) * PBW + ncol];
                if (BSPLIT) {
                    bfl[nt][0] = smw[SBL_OFF(stg) + (kpb    ) * PBW + ncol];
                    bfl[nt][1] = smw[SBL_OFF(stg) + (kpb + 4) * PBW + ncol];
                }
            }
            // ---- A fragments via ldmatrix.x4 (one per mt) ----
            uint32_t af[4][4];
#pragma unroll
            for (int mt = 0; mt < 4; mt++)
                LDSM4(af[mt], abase + (uint32_t)(mt * 16 * PAW + s * 8) * 4u);

#pragma unroll
            for (int mt = 0; mt < 4; mt++)
#pragma unroll
                for (int nt = 0; nt < 4; nt++)
                    MMA16816F16(acc[mt][nt], af[mt], bfh[nt]);
            if (BSPLIT) {
#pragma unroll
                for (int mt = 0; mt < 4; mt++)
#pragma unroll
                    for (int nt = 0; nt < 4; nt++)
                        MMA16816F16(acc[mt][nt], af[mt], bfl[nt]);
            }
        }
    }

    // ---- epilogue ----
    const float* sbias = smem + BIAS_OFF;
#pragma unroll
    for (int mt = 0; mt < 4; mt++) {
        int r0 = m0 + wm * 64 + mt * 16 + gid;
#pragma unroll
        for (int nt = 0; nt < 4; nt++) {
            int col = wn * 32 + nt * 8 + 2 * tig;
            float bv0 = sbias[col], bv1 = sbias[col + 1];
            float x0 = acc[mt][nt][0] + bv0;
            float x1 = acc[mt][nt][1] + bv1;
            float x2 = acc[mt][nt][2] + bv0;
            float x3 = acc[mt][nt][3] + bv1;
            if (relu) {
                x0 = fmaxf(x0, 0.f); x1 = fmaxf(x1, 0.f);
                x2 = fmaxf(x2, 0.f); x3 = fmaxf(x3, 0.f);
            }
            if (WH16) {
                int wcol = (n0 + col) >> 1;
                if (r0 < M)
                    C16[(size_t)r0 * 128 + wcol] = pack1h(x0, x1);
                if (r0 + 8 < M)
                    C16[(size_t)(r0 + 8) * 128 + wcol] = pack1h(x2, x3);
            } else {
                if (r0 < M)
                    *reinterpret_cast<float2*>(&Cout[(size_t)r0 * Nfull + n0 + col]) =
                        make_float2(x0, x1);
                if (r0 + 8 < M)
                    *reinterpret_cast<float2*>(&Cout[(size_t)(r0 + 8) * Nfull + n0 + col]) =
                        make_float2(x2, x3);
            }
        }
    }
}

// ===========================================================================
// Segment softmax: 256 threads, 8 rows in flight (q = tid/32), float4 cols.
// ===========================================================================
__device__ __forceinline__ int lower_bound_i32(const int* __restrict__ a,
                                               int n, int key)
{
    int lo = 0, hi = n;
    while (lo < hi) {
        int mid = (lo + hi) >> 1;
        if (a[mid] < key) lo = mid + 1; else hi = mid;
    }
    return lo;
}

__device__ __forceinline__ void upd(float& m, float& s, float x) {
    if (x > m) { s = s * __expf(m - x) + 1.f; m = x; }
    else       { s += __expf(x - m); }
}

__global__ __launch_bounds__(256) void seg_softmax(
    const float* __restrict__ logits,
    const int* __restrict__ batch,
    float* __restrict__ probs)
{
    __shared__ float sm_m[8 * 128];
    __shared__ float sm_s[8 * 128];

    const int s   = blockIdx.x;
    const int lo  = lower_bound_i32(batch, NN, s);
    const int hi  = lower_bound_i32(batch, NN, s + 1);
    const int q   = threadIdx.x >> 5;
    const int cb  = (threadIdx.x & 31) * 4;

    float m[4] = {-CUDART_INF_F, -CUDART_INF_F, -CUDART_INF_F, -CUDART_INF_F};
    float sum[4] = {0.f, 0.f, 0.f, 0.f};

    for (int r = lo + q; r < hi; r += 8) {
        float4 v = *reinterpret_cast<const float4*>(&logits[(size_t)r * CC + cb]);
        upd(m[0], sum[0], v.x);
        upd(m[1], sum[1], v.y);
        upd(m[2], sum[2], v.z);
        upd(m[3], sum[3], v.w);
    }
#pragma unroll
    for (int j = 0; j < 4; j++) {
        sm_m[q * 128 + cb + j] = m[j];
        sm_s[q * 128 + cb + j] = sum[j];
    }
    __syncthreads();

    if (threadIdx.x < 128) {
        const int c = threadIdx.x;
        float M = -CUDART_INF_F, S = 0.f;
#pragma unroll
        for (int qq = 0; qq < 8; qq++) {
            float mq = sm_m[qq * 128 + c], sq = sm_s[qq * 128 + c];
            if (sq > 0.f) {
                float nm = fmaxf(M, mq);
                S = S * __expf(M - nm) + sq * __expf(mq - nm);
                M = nm;
            }
        }
        sm_m[c] = M;
        sm_s[c] = (S > 0.f) ? (1.f / S) : 0.f;
    }
    __syncthreads();

    float mm[4], ii[4];
#pragma unroll
    for (int j = 0; j < 4; j++) { mm[j] = sm_m[cb + j]; ii[j] = sm_s[cb + j]; }

    for (int r = lo + q; r < hi; r += 8) {
        float4 v = *reinterpret_cast<const float4*>(&logits[(size_t)r * CC + cb]);
        float4 o;
        o.x = __expf(v.x - mm[0]) * ii[0];
        o.y = __expf(v.y - mm[1]) * ii[1];
        o.z = __expf(v.z - mm[2]) * ii[2];
        o.w = __expf(v.w - mm[3]) * ii[3];
        *reinterpret_cast<float4*>(&probs[(size_t)r * CC + cb]) = o;
    }
}

// ===========================================================================
// Launch
// ===========================================================================
extern "C" void kernel_launch(void* const* d_in, const int* in_sizes, int n_in,
                              void* d_out, int out_size)
{
    const float* H  = nullptr;
    const int*   batch = nullptr;
    const float* W1 = nullptr;
    const float* b1 = nullptr;
    const float* W2 = nullptr;
    const float* b2 = nullptr;

    for (int i = 0; i < n_in; i++) {
        switch (in_sizes[i]) {
            case 128000000: H     = (const float*)d_in[i]; break;
            case 500000:    batch = (const int*)d_in[i];   break;
            case 65536:     W1    = (const float*)d_in[i]; break;
            case 256:       b1    = (const float*)d_in[i]; break;
            case 32768:     W2    = (const float*)d_in[i]; break;
            case 128:       b2    = (const float*)d_in[i]; break;
            default: break;
        }
    }

    float* out    = (float*)d_out;
    float* logits = out;
    float* probs  = out + (size_t)NN * CC;

    void *a16, *h16, *w1hi, *w1lo, *w2hi, *w2lo;
    cudaGetSymbolAddress(&a16, g_a16);
    cudaGetSymbolAddress(&h16, g_h16);
    cudaGetSymbolAddress(&w1hi, g_w1hi);
    cudaGetSymbolAddress(&w1lo, g_w1lo);
    cudaGetSymbolAddress(&w2hi, g_w2hi);
    cudaGetSymbolAddress(&w2lo, g_w2lo);

    cudaFuncSetAttribute(gemm_hmma<1, 0>,
                         cudaFuncAttributeMaxDynamicSharedMemorySize, SMEM_BYTES);
    cudaFuncSetAttribute(gemm_hmma<0, 1>,
                         cudaFuncAttributeMaxDynamicSharedMemorySize, SMEM_BYTES);

    // Pre-convert H (fp32 -> fp16 words) and weights (fp32 -> fp16 hi/lo)
    convert_h<<<62500, 256>>>(H, (uint32_t*)a16);
    convert_w<<<192, 256>>>(W1, W2);

    const int mblocks = (NN + BM - 1) / BM;    // 3907

    // Layer 1: h = relu(H @ W1 + b1), single product (W1 hi), h -> fp16 words
    dim3 g1(mblocks, DD / BN);                 // 3907 x 2
    gemm_hmma<1, 0><<<g1, 256, SMEM_BYTES>>>(
        (const uint32_t*)a16, (const uint32_t*)w1hi, nullptr,
        b1, nullptr, (uint32_t*)h16, NN, DD, 1);

    // Layer 2: logits = h @ W2 + b2, 2-product (W2 split), fp32 out
    dim3 g2(mblocks, CC / BN);                 // 3907 x 1
    gemm_hmma<0, 1><<<g2, 256, SMEM_BYTES>>>(
        (const uint32_t*)h16, (const uint32_t*)w2hi, (const uint32_t*)w2lo,
        b2, logits, nullptr, NN, CC, 0);

    // Segment softmax -> probs
    seg_softmax<<<SSEG, 256>>>(logits, batch, probs);
}

// round 15
// speedup vs baseline: 1.2668x; 1.0178x over previous
#include <cuda_runtime.h>
#include <cuda_fp16.h>
#include <math_constants.h>
#include <cstdint>

#define NN 500000
#define DD 256
#define CC 128
#define SSEG 2048

#define BM 128
#define BN 128
#define BK 64
#define NCHUNK (DD / BK)     // 4
#define KP 128               // kp words per row in A16/h16 and per n-row in W
#define PAW 36               // A fp16-word pitch: LDSM phases hit all banks
#define PBW 36               // B fp16-word pitch [n][kp]: same property

// smem word offsets (27776 words = 111104 B; 2 CTAs/SM)
#define SAH_OFF(s)  ((s) * 4608)            // A: 128*36, 2 stages
#define SBH_OFF(s)  (9216 + (s) * 4608)     // B hi: 128 n-rows * 36
#define SBL_OFF(s)  (18432 + (s) * 4608)    // B lo
#define BIAS_OFF    27648
#define SMEM_BYTES  (27776 * 4)

// H pre-converted to fp16x2 words [m][kp]: 256 MB.
__device__ uint32_t g_a16[(long long)NN * KP];
// h stored as fp16x2 words [m][kp]: 256 MB.
__device__ uint32_t g_h16[(long long)NN * KP];
// pre-split weights (fp16 hi/lo), word layout [n][kp]
__device__ uint32_t g_w1hi[256 * KP], g_w1lo[256 * KP];
__device__ uint32_t g_w2hi[128 * KP], g_w2lo[128 * KP];

#define MMA16816F16(d, a, b)                                                  \
    asm volatile(                                                             \
        "mma.sync.aligned.m16n8k16.row.col.f32.f16.f16.f32 "                  \
        "{%0,%1,%2,%3}, {%4,%5,%6,%7}, {%8,%9}, {%0,%1,%2,%3};"               \
        : "+f"((d)[0]), "+f"((d)[1]), "+f"((d)[2]), "+f"((d)[3])              \
        : "r"((a)[0]), "r"((a)[1]), "r"((a)[2]), "r"((a)[3]),                 \
          "r"((b)[0]), "r"((b)[1]))

#define LDSM4(r, addr)                                                        \
    asm volatile("ldmatrix.sync.aligned.m8n8.x4.shared.b16 {%0,%1,%2,%3}, [%4];" \
        : "=r"((r)[0]), "=r"((r)[1]), "=r"((r)[2]), "=r"((r)[3]) : "r"(addr))

__device__ __forceinline__ uint32_t pack1h(float x, float y) {
    __half2 h = __floats2half2_rn(x, y);
    return *reinterpret_cast<uint32_t*>(&h);
}
__device__ __forceinline__ void pack2h(float x, float y, uint32_t& hi, uint32_t& lo) {
    __half2 h = __floats2half2_rn(x, y);
    hi = *reinterpret_cast<uint32_t*>(&h);
    float rx = x - __low2float(h);
    float ry = y - __high2float(h);
    __half2 l = __floats2half2_rn(rx, ry);
    lo = *reinterpret_cast<uint32_t*>(&l);
}

__device__ __forceinline__ void cpa16(uint32_t dst, const void* src, int srcsz) {
    asm volatile("cp.async.cg.shared.global [%0], [%1], 16, %2;"
                 :: "r"(dst), "l"(src), "r"(srcsz));
}
#define CP_COMMIT()  asm volatile("cp.async.commit_group;" ::: "memory")
#define CP_WAIT0()   asm volatile("cp.async.wait_group 0;" ::: "memory")

// ===========================================================================
// H pre-conversion: fp32 -> fp16x2 words. 8 floats / thread.
// ===========================================================================
__global__ __launch_bounds__(256) void convert_h(
    const float* __restrict__ H, uint32_t* __restrict__ A16)
{
    size_t i = (size_t)blockIdx.x * 256 + threadIdx.x;   // < 16,000,000
    const float4* src = reinterpret_cast<const float4*>(H);
    float4 a = src[2 * i], b = src[2 * i + 1];
    uint4 o;
    o.x = pack1h(a.x, a.y);  o.y = pack1h(a.z, a.w);
    o.z = pack1h(b.x, b.y);  o.w = pack1h(b.z, b.w);
    reinterpret_cast<uint4*>(A16)[i] = o;
}

// ===========================================================================
// Weight pre-split: W[k][n] fp32 -> fp16 hi/lo words, [n][kp] layout
// ===========================================================================
__global__ __launch_bounds__(256) void convert_w(
    const float* __restrict__ W1, const float* __restrict__ W2)
{
    int idx = blockIdx.x * 256 + threadIdx.x;
    if (idx < 256 * KP) {
        int n = idx >> 7, kp = idx & 127;
        uint32_t hi, lo;
        pack2h(W1[(2 * kp) * 256 + n], W1[(2 * kp + 1) * 256 + n], hi, lo);
        g_w1hi[idx] = hi; g_w1lo[idx] = lo;
    } else {
        int j = idx - 256 * KP;
        if (j < 128 * KP) {
            int n = j >> 7, kp = j & 127;
            uint32_t hi, lo;
            pack2h(W2[(2 * kp) * 128 + n], W2[(2 * kp + 1) * 128 + n], hi, lo);
            g_w2hi[j] = hi; g_w2lo[j] = lo;
        }
    }
}

// ===========================================================================
// HMMA fp16 GEMM: A and B fp16 words via cp.async + ldmatrix. BK=64, 2-stage.
// WH16:  write packed fp16 words (h) vs fp32 (logits)
// BSPLIT: B = hi+lo 2-product vs hi-only single product
// CTA 128x128, 8 warps (2m x 4n), warp tile 64x32.
// Grid: (n-tiles, m-tiles) so CTAs sharing an A tile are schedule-adjacent.
// ===========================================================================
template <int WH16, int BSPLIT>
__global__ __launch_bounds__(256, 2)
void gemm_hmma(const uint32_t* __restrict__ A16,
               const uint32_t* __restrict__ Bhi, const uint32_t* __restrict__ Blo,
               const float* __restrict__ bias,
               float* __restrict__ Cout, uint32_t* __restrict__ C16,
               int M, int Nfull, int relu)
{
    extern __shared__ float smem[];
    const uint32_t smem32 = (uint32_t)__cvta_generic_to_shared(smem);

    const int tid  = threadIdx.x;
    const int lane = tid & 31;
    const int wid  = tid >> 5;
    const int wm   = wid & 1;
    const int wn   = wid >> 1;
    const int gid  = lane >> 2;
    const int tig  = lane & 3;
    const int m0   = blockIdx.y * BM;
    const int n0   = blockIdx.x * BN;

    if (tid < BN) smem[BIAS_OFF + tid] = bias[n0 + tid];

    float acc[4][4][4];
#pragma unroll
    for (int mt = 0; mt < 4; mt++)
#pragma unroll
        for (int nt = 0; nt < 4; nt++)
#pragma unroll
            for (int i = 0; i < 4; i++) acc[mt][nt][i] = 0.f;

    auto issue_chunk = [&](int c, int stg) {
        // A: 128 rows x 32 words -> 1024 cpa16 / 256 thr = 4 each
#pragma unroll
        for (int l = 0; l < 4; l++) {
            int o = tid + 256 * l;
            int row = o >> 3, seg = o & 7;
            int grow = m0 + row;
            int ok = (grow < M);
            cpa16(smem32 + (uint32_t)(SAH_OFF(stg) + row * PAW + seg * 4) * 4u,
                  &A16[(size_t)(ok ? grow : 0) * KP + c * 32 + seg * 4], ok ? 16 : 0);
        }
        // B: 128 n-rows x 32 words -> 4 each (x2 if split)
#pragma unroll
        for (int l = 0; l < 4; l++) {
            int o = tid + 256 * l;
            int row = o >> 3, seg = o & 7;
            cpa16(smem32 + (uint32_t)(SBH_OFF(stg) + row * PBW + seg * 4) * 4u,
                  &Bhi[(size_t)(n0 + row) * KP + c * 32 + seg * 4], 16);
            if (BSPLIT)
                cpa16(smem32 + (uint32_t)(SBL_OFF(stg) + row * PBW + seg * 4) * 4u,
                      &Blo[(size_t)(n0 + row) * KP + c * 32 + seg * 4], 16);
        }
        CP_COMMIT();
    };

    // per-lane LDSM bases (words, stage-relative)
    const int abase_rel = (wm * 64 + (lane & 15)) * PAW + (lane >> 4) * 4;
    const int bgrp = lane >> 3;        // 0..3
    const int brow = lane & 7;
    const int bbase_rel = (wn * 32 + (bgrp >> 1) * 8 + brow) * PBW + (bgrp & 1) * 4;

    issue_chunk(0, 0);

#pragma unroll 1
    for (int c = 0; c < NCHUNK; c++) {
        const int stg = c & 1;
        CP_WAIT0();
        __syncthreads();
        if (c < NCHUNK - 1) issue_chunk(c + 1, stg ^ 1);

        const uint32_t abase  = smem32 + (uint32_t)(SAH_OFF(stg) + abase_rel) * 4u;
        const uint32_t bhbase = smem32 + (uint32_t)(SBH_OFF(stg) + bbase_rel) * 4u;
        const uint32_t blbase = smem32 + (uint32_t)(SBL_OFF(stg) + bbase_rel) * 4u;

#pragma unroll
        for (int s = 0; s < 4; s++) {             // 4 x k16 per chunk
            // ---- B fragments via ldmatrix.x4 (2 nt per LDSM) ----
            uint32_t bfh[4][2], bfl[4][2];
#pragma unroll
            for (int np = 0; np < 2; np++) {      // nt pairs (0,1), (2,3)
                uint32_t t[4];
                LDSM4(t, bhbase + (uint32_t)(np * 16 * PBW + s * 8) * 4u);
                bfh[2 * np][0] = t[0];  bfh[2 * np][1] = t[1];
                bfh[2 * np + 1][0] = t[2];  bfh[2 * np + 1][1] = t[3];
                if (BSPLIT) {
                    LDSM4(t, blbase + (uint32_t)(np * 16 * PBW + s * 8) * 4u);
                    bfl[2 * np][0] = t[0];  bfl[2 * np][1] = t[1];
                    bfl[2 * np + 1][0] = t[2];  bfl[2 * np + 1][1] = t[3];
                }
            }
            // ---- A fragments via ldmatrix.x4 (one per mt) ----
            uint32_t af[4][4];
#pragma unroll
            for (int mt = 0; mt < 4; mt++)
                LDSM4(af[mt], abase + (uint32_t)(mt * 16 * PAW + s * 8) * 4u);

#pragma unroll
            for (int mt = 0; mt < 4; mt++)
#pragma unroll
                for (int nt = 0; nt < 4; nt++)
                    MMA16816F16(acc[mt][nt], af[mt], bfh[nt]);
            if (BSPLIT) {
#pragma unroll
                for (int mt = 0; mt < 4; mt++)
#pragma unroll
                    for (int nt = 0; nt < 4; nt++)
                        MMA16816F16(acc[mt][nt], af[mt], bfl[nt]);
            }
        }
    }

    // ---- epilogue ----
    const float* sbias = smem + BIAS_OFF;
#pragma unroll
    for (int mt = 0; mt < 4; mt++) {
        int r0 = m0 + wm * 64 + mt * 16 + gid;
#pragma unroll
        for (int nt = 0; nt < 4; nt++) {
            int col = wn * 32 + nt * 8 + 2 * tig;
            float bv0 = sbias[col], bv1 = sbias[col + 1];
            float x0 = acc[mt][nt][0] + bv0;
            float x1 = acc[mt][nt][1] + bv1;
            float x2 = acc[mt][nt][2] + bv0;
            float x3 = acc[mt][nt][3] + bv1;
            if (relu) {
                x0 = fmaxf(x0, 0.f); x1 = fmaxf(x1, 0.f);
                x2 = fmaxf(x2, 0.f); x3 = fmaxf(x3, 0.f);
            }
            if (WH16) {
                int wcol = (n0 + col) >> 1;
                if (r0 < M)
                    C16[(size_t)r0 * KP + wcol] = pack1h(x0, x1);
                if (r0 + 8 < M)
                    C16[(size_t)(r0 + 8) * KP + wcol] = pack1h(x2, x3);
            } else {
                if (r0 < M)
                    *reinterpret_cast<float2*>(&Cout[(size_t)r0 * Nfull + n0 + col]) =
                        make_float2(x0, x1);
                if (r0 + 8 < M)
                    *reinterpret_cast<float2*>(&Cout[(size_t)(r0 + 8) * Nfull + n0 + col]) =
                        make_float2(x2, x3);
            }
        }
    }
}

// ===========================================================================
// Segment softmax: 256 threads, unroll x2 (rows r, r+8), float4 cols.
// ===========================================================================
__device__ __forceinline__ int lower_bound_i32(const int* __restrict__ a,
                                               int n, int key)
{
    int lo = 0, hi = n;
    while (lo < hi) {
        int mid = (lo + hi) >> 1;
        if (a[mid] < key) lo = mid + 1; else hi = mid;
    }
    return lo;
}

__device__ __forceinline__ void upd(float& m, float& s, float x) {
    if (x > m) { s = s * __expf(m - x) + 1.f; m = x; }
    else       { s += __expf(x - m); }
}

__global__ __launch_bounds__(256) void seg_softmax(
    const float* __restrict__ logits,
    const int* __restrict__ batch,
    float* __restrict__ probs)
{
    __shared__ float sm_m[8 * 128];
    __shared__ float sm_s[8 * 128];

    const int s   = blockIdx.x;
    const int lo  = lower_bound_i32(batch, NN, s);
    const int hi  = lower_bound_i32(batch, NN, s + 1);
    const int q   = threadIdx.x >> 5;
    const int cb  = (threadIdx.x & 31) * 4;

    float m[4] = {-CUDART_INF_F, -CUDART_INF_F, -CUDART_INF_F, -CUDART_INF_F};
    float sum[4] = {0.f, 0.f, 0.f, 0.f};

    int r = lo + q;
    for (; r + 8 < hi; r += 16) {
        float4 v1 = *reinterpret_cast<const float4*>(&logits[(size_t)r * CC + cb]);
        float4 v2 = *reinterpret_cast<const float4*>(&logits[(size_t)(r + 8) * CC + cb]);
        upd(m[0], sum[0], v1.x);  upd(m[1], sum[1], v1.y);
        upd(m[2], sum[2], v1.z);  upd(m[3], sum[3], v1.w);
        upd(m[0], sum[0], v2.x);  upd(m[1], sum[1], v2.y);
        upd(m[2], sum[2], v2.z);  upd(m[3], sum[3], v2.w);
    }
    if (r < hi) {
        float4 v1 = *reinterpret_cast<const float4*>(&logits[(size_t)r * CC + cb]);
        upd(m[0], sum[0], v1.x);  upd(m[1], sum[1], v1.y);
        upd(m[2], sum[2], v1.z);  upd(m[3], sum[3], v1.w);
    }
#pragma unroll
    for (int j = 0; j < 4; j++) {
        sm_m[q * 128 + cb + j] = m[j];
        sm_s[q * 128 + cb + j] = sum[j];
    }
    __syncthreads();

    if (threadIdx.x < 128) {
        const int c = threadIdx.x;
        float M = -CUDART_INF_F, S = 0.f;
#pragma unroll
        for (int qq = 0; qq < 8; qq++) {
            float mq = sm_m[qq * 128 + c], sq = sm_s[qq * 128 + c];
            if (sq > 0.f) {
                float nm = fmaxf(M, mq);
                S = S * __expf(M - nm) + sq * __expf(mq - nm);
                M = nm;
            }
        }
        sm_m[c] = M;
        sm_s[c] = (S > 0.f) ? (1.f / S) : 0.f;
    }
    __syncthreads();

    float mm[4], ii[4];
#pragma unroll
    for (int j = 0; j < 4; j++) { mm[j] = sm_m[cb + j]; ii[j] = sm_s[cb + j]; }

    r = lo + q;
    for (; r + 8 < hi; r += 16) {
        float4 v1 = *reinterpret_cast<const float4*>(&logits[(size_t)r * CC + cb]);
        float4 v2 = *reinterpret_cast<const float4*>(&logits[(size_t)(r + 8) * CC + cb]);
        float4 o1, o2;
        o1.x = __expf(v1.x - mm[0]) * ii[0];  o1.y = __expf(v1.y - mm[1]) * ii[1];
        o1.z = __expf(v1.z - mm[2]) * ii[2];  o1.w = __expf(v1.w - mm[3]) * ii[3];
        o2.x = __expf(v2.x - mm[0]) * ii[0];  o2.y = __expf(v2.y - mm[1]) * ii[1];
        o2.z = __expf(v2.z - mm[2]) * ii[2];  o2.w = __expf(v2.w - mm[3]) * ii[3];
        *reinterpret_cast<float4*>(&probs[(size_t)r * CC + cb]) = o1;
        *reinterpret_cast<float4*>(&probs[(size_t)(r + 8) * CC + cb]) = o2;
    }
    if (r < hi) {
        float4 v1 = *reinterpret_cast<const float4*>(&logits[(size_t)r * CC + cb]);
        float4 o1;
        o1.x = __expf(v1.x - mm[0]) * ii[0];  o1.y = __expf(v1.y - mm[1]) * ii[1];
        o1.z = __expf(v1.z - mm[2]) * ii[2];  o1.w = __expf(v1.w - mm[3]) * ii[3];
        *reinterpret_cast<float4*>(&probs[(size_t)r * CC + cb]) = o1;
    }
}

// ===========================================================================
// Launch
// ===========================================================================
extern "C" void kernel_launch(void* const* d_in, const int* in_sizes, int n_in,
                              void* d_out, int out_size)
{
    const float* H  = nullptr;
    const int*   batch = nullptr;
    const float* W1 = nullptr;
    const float* b1 = nullptr;
    const float* W2 = nullptr;
    const float* b2 = nullptr;

    for (int i = 0; i < n_in; i++) {
        switch (in_sizes[i]) {
            case 128000000: H     = (const float*)d_in[i]; break;
            case 500000:    batch = (const int*)d_in[i];   break;
            case 65536:     W1    = (const float*)d_in[i]; break;
            case 256:       b1    = (const float*)d_in[i]; break;
            case 32768:     W2    = (const float*)d_in[i]; break;
            case 128:       b2    = (const float*)d_in[i]; break;
            default: break;
        }
    }

    float* out    = (float*)d_out;
    float* logits = out;
    float* probs  = out + (size_t)NN * CC;

    void *a16, *h16, *w1hi, *w1lo, *w2hi, *w2lo;
    cudaGetSymbolAddress(&a16, g_a16);
    cudaGetSymbolAddress(&h16, g_h16);
    cudaGetSymbolAddress(&w1hi, g_w1hi);
    cudaGetSymbolAddress(&w1lo, g_w1lo);
    cudaGetSymbolAddress(&w2hi, g_w2hi);
    cudaGetSymbolAddress(&w2lo, g_w2lo);

    cudaFuncSetAttribute(gemm_hmma<1, 0>,
                         cudaFuncAttributeMaxDynamicSharedMemorySize, SMEM_BYTES);
    cudaFuncSetAttribute(gemm_hmma<0, 1>,
                         cudaFuncAttributeMaxDynamicSharedMemorySize, SMEM_BYTES);

    // Pre-convert H (fp32 -> fp16 words) and weights (fp32 -> fp16 hi/lo [n][kp])
    convert_h<<<62500, 256>>>(H, (uint32_t*)a16);
    convert_w<<<192, 256>>>(W1, W2);

    const int mblocks = (NN + BM - 1) / BM;    // 3907

    // Layer 1: h = relu(H @ W1 + b1), single product (W1 hi), h -> fp16 words
    dim3 g1(DD / BN, mblocks);                 // 2 x 3907 (A-tile pairs adjacent)
    gemm_hmma<1, 0><<<g1, 256, SMEM_BYTES>>>(
        (const uint32_t*)a16, (const uint32_t*)w1hi, nullptr,
        b1, nullptr, (uint32_t*)h16, NN, DD, 1);

    // Layer 2: logits = h @ W2 + b2, 2-product (W2 split), fp32 out
    dim3 g2(CC / BN, mblocks);                 // 1 x 3907
    gemm_hmma<0, 1><<<g2, 256, SMEM_BYTES>>>(
        (const uint32_t*)h16, (const uint32_t*)w2hi, (const uint32_t*)w2lo,
        b2, logits, nullptr, NN, CC, 0);

    // Segment softmax -> probs
    seg_softmax<<<SSEG, 256>>>(logits, batch, probs);
}

// round 16
// speedup vs baseline: 1.3893x; 1.0967x over previous
#include <cuda_runtime.h>
#include <cuda_fp16.h>
#include <math_constants.h>
#include <cstdint>

#define NN 500000
#define DD 256
#define CC 128
#define SSEG 2048

#define BM 128
#define BN 128
#define BK 64
#define NCHUNK (DD / BK)     // 4
#define KP 128               // kp words per row (h16 / W arrays)
#define PA32 72              // A fp32 pitch (64+8): %32==8 -> conflict-free LDS.64
#define PAW 36               // A fp16-word pitch (gemm2): LDSM conflict-free
#define PBW 36               // B fp16-word pitch [n][kp]: LDSM conflict-free

#define BIAS_OFF    27648
#define SMEM_BYTES  ((27648 + 128) * 4)     // 111104 B; 2 CTAs/SM

// h stored as fp16x2 words [m][kp]: 256 MB.
__device__ uint32_t g_h16[(long long)NN * KP];
// pre-split weights (fp16 hi/lo), word layout [n][kp]
__device__ uint32_t g_w1hi[256 * KP], g_w1lo[256 * KP];
__device__ uint32_t g_w2hi[128 * KP], g_w2lo[128 * KP];

#define MMA16816F16(d, a, b)                                                  \
    asm volatile(                                                             \
        "mma.sync.aligned.m16n8k16.row.col.f32.f16.f16.f32 "                  \
        "{%0,%1,%2,%3}, {%4,%5,%6,%7}, {%8,%9}, {%0,%1,%2,%3};"               \
        : "+f"((d)[0]), "+f"((d)[1]), "+f"((d)[2]), "+f"((d)[3])              \
        : "r"((a)[0]), "r"((a)[1]), "r"((a)[2]), "r"((a)[3]),                 \
          "r"((b)[0]), "r"((b)[1]))

#define LDSM4(r, addr)                                                        \
    asm volatile("ldmatrix.sync.aligned.m8n8.x4.shared.b16 {%0,%1,%2,%3}, [%4];" \
        : "=r"((r)[0]), "=r"((r)[1]), "=r"((r)[2]), "=r"((r)[3]) : "r"(addr))

__device__ __forceinline__ uint32_t pack1h(float x, float y) {
    __half2 h = __floats2half2_rn(x, y);
    return *reinterpret_cast<uint32_t*>(&h);
}
__device__ __forceinline__ void pack2h(float x, float y, uint32_t& hi, uint32_t& lo) {
    __half2 h = __floats2half2_rn(x, y);
    hi = *reinterpret_cast<uint32_t*>(&h);
    float rx = x - __low2float(h);
    float ry = y - __high2float(h);
    __half2 l = __floats2half2_rn(rx, ry);
    lo = *reinterpret_cast<uint32_t*>(&l);
}

__device__ __forceinline__ void cpa16(uint32_t dst, const void* src, int srcsz) {
    asm volatile("cp.async.cg.shared.global [%0], [%1], 16, %2;"
                 :: "r"(dst), "l"(src), "r"(srcsz));
}
#define CP_COMMIT()  asm volatile("cp.async.commit_group;" ::: "memory")
#define CP_WAIT0()   asm volatile("cp.async.wait_group 0;" ::: "memory")

// ===========================================================================
// Weight pre-split: W[k][n] fp32 -> fp16 hi/lo words, [n][kp] layout
// ===========================================================================
__global__ __launch_bounds__(256) void convert_w(
    const float* __restrict__ W1, const float* __restrict__ W2)
{
    int idx = blockIdx.x * 256 + threadIdx.x;
    if (idx < 256 * KP) {
        int n = idx >> 7, kp = idx & 127;
        uint32_t hi, lo;
        pack2h(W1[(2 * kp) * 256 + n], W1[(2 * kp + 1) * 256 + n], hi, lo);
        g_w1hi[idx] = hi; g_w1lo[idx] = lo;
    } else {
        int j = idx - 256 * KP;
        if (j < 128 * KP) {
            int n = j >> 7, kp = j & 127;
            uint32_t hi, lo;
            pack2h(W2[(2 * kp) * 128 + n], W2[(2 * kp + 1) * 128 + n], hi, lo);
            g_w2hi[j] = hi; g_w2lo[j] = lo;
        }
    }
}

// ===========================================================================
// HMMA fp16 GEMM. BK=64, 2-stage cp.async, B via n-major ldmatrix.
// AFP32:  A staged as fp32 (LDS.64 + pack at frag load) vs fp16 words + LDSM
// WH16:   write packed fp16 words (h) vs fp32 (logits)
// BSPLIT: B = hi+lo 2-product vs hi-only single product
// CTA 128x128, 8 warps (2m x 4n), warp tile 64x32.
// Grid: (n-tiles, m-tiles) so CTAs sharing an A tile are schedule-adjacent.
// ===========================================================================
template <int AFP32, int WH16, int BSPLIT>
__global__ __launch_bounds__(256, 2)
void gemm_hmma(const float* __restrict__ A32,
               const uint32_t* __restrict__ A16,
               const uint32_t* __restrict__ Bhi, const uint32_t* __restrict__ Blo,
               const float* __restrict__ bias,
               float* __restrict__ Cout, uint32_t* __restrict__ C16,
               int M, int Nfull, int relu)
{
    extern __shared__ float smem[];
    const uint32_t smem32 = (uint32_t)__cvta_generic_to_shared(smem);

    const int tid  = threadIdx.x;
    const int lane = tid & 31;
    const int wid  = tid >> 5;
    const int wm   = wid & 1;
    const int wn   = wid >> 1;
    const int gid  = lane >> 2;
    const int tig  = lane & 3;
    const int m0   = blockIdx.y * BM;
    const int n0   = blockIdx.x * BN;

    // smem word offsets (template-dependent)
    auto sa_off  = [](int s) { return AFP32 ? s * 9216 : s * 4608; };
    auto sbh_off = [](int s) { return AFP32 ? 18432 + s * 4608 : 9216 + s * 4608; };
    auto sbl_off = [](int s) { return 18432 + s * 4608; };   // only used if !AFP32

    if (tid < BN) smem[BIAS_OFF + tid] = bias[n0 + tid];

    float acc[4][4][4];
#pragma unroll
    for (int mt = 0; mt < 4; mt++)
#pragma unroll
        for (int nt = 0; nt < 4; nt++)
#pragma unroll
            for (int i = 0; i < 4; i++) acc[mt][nt][i] = 0.f;

    auto issue_chunk = [&](int c, int stg) {
        if (AFP32) {
            // A fp32: 128 rows x 64 floats = 2048 cpa16 -> 8 per thread
#pragma unroll
            for (int l = 0; l < 8; l++) {
                int o = tid + 256 * l;
                int row = o >> 4, seg = o & 15;
                int grow = m0 + row;
                int ok = (grow < M);
                cpa16(smem32 + (uint32_t)(sa_off(stg) + row * PA32 + seg * 4) * 4u,
                      &A32[(size_t)(ok ? grow : 0) * DD + c * BK + seg * 4], ok ? 16 : 0);
            }
        } else {
            // A fp16 words: 128 rows x 32 words -> 4 per thread
#pragma unroll
            for (int l = 0; l < 4; l++) {
                int o = tid + 256 * l;
                int row = o >> 3, seg = o & 7;
                int grow = m0 + row;
                int ok = (grow < M);
                cpa16(smem32 + (uint32_t)(sa_off(stg) + row * PAW + seg * 4) * 4u,
                      &A16[(size_t)(ok ? grow : 0) * KP + c * 32 + seg * 4], ok ? 16 : 0);
            }
        }
        // B: 128 n-rows x 32 words -> 4 per thread (x2 if split)
#pragma unroll
        for (int l = 0; l < 4; l++) {
            int o = tid + 256 * l;
            int row = o >> 3, seg = o & 7;
            cpa16(smem32 + (uint32_t)(sbh_off(stg) + row * PBW + seg * 4) * 4u,
                  &Bhi[(size_t)(n0 + row) * KP + c * 32 + seg * 4], 16);
            if (BSPLIT)
                cpa16(smem32 + (uint32_t)(sbl_off(stg) + row * PBW + seg * 4) * 4u,
                      &Blo[(size_t)(n0 + row) * KP + c * 32 + seg * 4], 16);
        }
        CP_COMMIT();
    };

    // per-lane LDSM bases (words, stage-relative)
    const int abase_rel = (wm * 64 + (lane & 15)) * PAW + (lane >> 4) * 4;   // !AFP32
    const int bgrp = lane >> 3;
    const int brow = lane & 7;
    const int bbase_rel = (wn * 32 + (bgrp >> 1) * 8 + brow) * PBW + (bgrp & 1) * 4;

    issue_chunk(0, 0);

#pragma unroll 1
    for (int c = 0; c < NCHUNK; c++) {
        const int stg = c & 1;
        CP_WAIT0();
        __syncthreads();
        if (c < NCHUNK - 1) issue_chunk(c + 1, stg ^ 1);

        const uint32_t bhbase = smem32 + (uint32_t)(sbh_off(stg) + bbase_rel) * 4u;
        const uint32_t blbase = smem32 + (uint32_t)(sbl_off(stg) + bbase_rel) * 4u;
        const float*   sA32   = smem + sa_off(stg);
        const uint32_t abase  = smem32 + (uint32_t)(sa_off(stg) + abase_rel) * 4u;

#pragma unroll
        for (int s = 0; s < 4; s++) {             // 4 x k16 per chunk
            // ---- B fragments via ldmatrix.x4 (2 nt per LDSM) ----
            uint32_t bfh[4][2], bfl[4][2];
#pragma unroll
            for (int np = 0; np < 2; np++) {
                uint32_t t[4];
                LDSM4(t, bhbase + (uint32_t)(np * 16 * PBW + s * 8) * 4u);
                bfh[2 * np][0] = t[0];      bfh[2 * np][1] = t[1];
                bfh[2 * np + 1][0] = t[2];  bfh[2 * np + 1][1] = t[3];
                if (BSPLIT) {
                    LDSM4(t, blbase + (uint32_t)(np * 16 * PBW + s * 8) * 4u);
                    bfl[2 * np][0] = t[0];      bfl[2 * np][1] = t[1];
                    bfl[2 * np + 1][0] = t[2];  bfl[2 * np + 1][1] = t[3];
                }
            }
            // ---- A fragments ----
            uint32_t af[4][4];
#pragma unroll
            for (int mt = 0; mt < 4; mt++) {
                if (AFP32) {
                    int mrow = wm * 64 + mt * 16 + gid;
                    int kb = 16 * s + 2 * tig;
                    float2 f0 = *reinterpret_cast<const float2*>(&sA32[(mrow    ) * PA32 + kb    ]);
                    float2 f1 = *reinterpret_cast<const float2*>(&sA32[(mrow + 8) * PA32 + kb    ]);
                    float2 f2 = *reinterpret_cast<const float2*>(&sA32[(mrow    ) * PA32 + kb + 8]);
                    float2 f3 = *reinterpret_cast<const float2*>(&sA32[(mrow + 8) * PA32 + kb + 8]);
                    af[mt][0] = pack1h(f0.x, f0.y);
                    af[mt][1] = pack1h(f1.x, f1.y);
                    af[mt][2] = pack1h(f2.x, f2.y);
                    af[mt][3] = pack1h(f3.x, f3.y);
                } else {
                    LDSM4(af[mt], abase + (uint32_t)(mt * 16 * PAW + s * 8) * 4u);
                }
            }

#pragma unroll
            for (int mt = 0; mt < 4; mt++)
#pragma unroll
                for (int nt = 0; nt < 4; nt++)
                    MMA16816F16(acc[mt][nt], af[mt], bfh[nt]);
            if (BSPLIT) {
#pragma unroll
                for (int mt = 0; mt < 4; mt++)
#pragma unroll
                    for (int nt = 0; nt < 4; nt++)
                        MMA16816F16(acc[mt][nt], af[mt], bfl[nt]);
            }
        }
    }

    // ---- epilogue ----
    const float* sbias = smem + BIAS_OFF;
#pragma unroll
    for (int mt = 0; mt < 4; mt++) {
        int r0 = m0 + wm * 64 + mt * 16 + gid;
#pragma unroll
        for (int nt = 0; nt < 4; nt++) {
            int col = wn * 32 + nt * 8 + 2 * tig;
            float bv0 = sbias[col], bv1 = sbias[col + 1];
            float x0 = acc[mt][nt][0] + bv0;
            float x1 = acc[mt][nt][1] + bv1;
            float x2 = acc[mt][nt][2] + bv0;
            float x3 = acc[mt][nt][3] + bv1;
            if (relu) {
                x0 = fmaxf(x0, 0.f); x1 = fmaxf(x1, 0.f);
                x2 = fmaxf(x2, 0.f); x3 = fmaxf(x3, 0.f);
            }
            if (WH16) {
                int wcol = (n0 + col) >> 1;
                if (r0 < M)
                    C16[(size_t)r0 * KP + wcol] = pack1h(x0, x1);
                if (r0 + 8 < M)
                    C16[(size_t)(r0 + 8) * KP + wcol] = pack1h(x2, x3);
            } else {
                if (r0 < M)
                    *reinterpret_cast<float2*>(&Cout[(size_t)r0 * Nfull + n0 + col]) =
                        make_float2(x0, x1);
                if (r0 + 8 < M)
                    *reinterpret_cast<float2*>(&Cout[(size_t)(r0 + 8) * Nfull + n0 + col]) =
                        make_float2(x2, x3);
            }
        }
    }
}

// ===========================================================================
// Segment softmax: 256 threads, unroll x2 (rows r, r+8), float4 cols.
// ===========================================================================
__device__ __forceinline__ int lower_bound_i32(const int* __restrict__ a,
                                               int n, int key)
{
    int lo = 0, hi = n;
    while (lo < hi) {
        int mid = (lo + hi) >> 1;
        if (a[mid] < key) lo = mid + 1; else hi = mid;
    }
    return lo;
}

__device__ __forceinline__ void upd(float& m, float& s, float x) {
    if (x > m) { s = s * __expf(m - x) + 1.f; m = x; }
    else       { s += __expf(x - m); }
}

__global__ __launch_bounds__(256) void seg_softmax(
    const float* __restrict__ logits,
    const int* __restrict__ batch,
    float* __restrict__ probs)
{
    __shared__ float sm_m[8 * 128];
    __shared__ float sm_s[8 * 128];

    const int s   = blockIdx.x;
    const int lo  = lower_bound_i32(batch, NN, s);
    const int hi  = lower_bound_i32(batch, NN, s + 1);
    const int q   = threadIdx.x >> 5;
    const int cb  = (threadIdx.x & 31) * 4;

    float m[4] = {-CUDART_INF_F, -CUDART_INF_F, -CUDART_INF_F, -CUDART_INF_F};
    float sum[4] = {0.f, 0.f, 0.f, 0.f};

    int r = lo + q;
    for (; r + 8 < hi; r += 16) {
        float4 v1 = *reinterpret_cast<const float4*>(&logits[(size_t)r * CC + cb]);
        float4 v2 = *reinterpret_cast<const float4*>(&logits[(size_t)(r + 8) * CC + cb]);
        upd(m[0], sum[0], v1.x);  upd(m[1], sum[1], v1.y);
        upd(m[2], sum[2], v1.z);  upd(m[3], sum[3], v1.w);
        upd(m[0], sum[0], v2.x);  upd(m[1], sum[1], v2.y);
        upd(m[2], sum[2], v2.z);  upd(m[3], sum[3], v2.w);
    }
    if (r < hi) {
        float4 v1 = *reinterpret_cast<const float4*>(&logits[(size_t)r * CC + cb]);
        upd(m[0], sum[0], v1.x);  upd(m[1], sum[1], v1.y);
        upd(m[2], sum[2], v1.z);  upd(m[3], sum[3], v1.w);
    }
#pragma unroll
    for (int j = 0; j < 4; j++) {
        sm_m[q * 128 + cb + j] = m[j];
        sm_s[q * 128 + cb + j] = sum[j];
    }
    __syncthreads();

    if (threadIdx.x < 128) {
        const int c = threadIdx.x;
        float M = -CUDART_INF_F, S = 0.f;
#pragma unroll
        for (int qq = 0; qq < 8; qq++) {
            float mq = sm_m[qq * 128 + c], sq = sm_s[qq * 128 + c];
            if (sq > 0.f) {
                float nm = fmaxf(M, mq);
                S = S * __expf(M - nm) + sq * __expf(mq - nm);
                M = nm;
            }
        }
        sm_m[c] = M;
        sm_s[c] = (S > 0.f) ? (1.f / S) : 0.f;
    }
    __syncthreads();

    float mm[4], ii[4];
#pragma unroll
    for (int j = 0; j < 4; j++) { mm[j] = sm_m[cb + j]; ii[j] = sm_s[cb + j]; }

    r = lo + q;
    for (; r + 8 < hi; r += 16) {
        float4 v1 = *reinterpret_cast<const float4*>(&logits[(size_t)r * CC + cb]);
        float4 v2 = *reinterpret_cast<const float4*>(&logits[(size_t)(r + 8) * CC + cb]);
        float4 o1, o2;
        o1.x = __expf(v1.x - mm[0]) * ii[0];  o1.y = __expf(v1.y - mm[1]) * ii[1];
        o1.z = __expf(v1.z - mm[2]) * ii[2];  o1.w = __expf(v1.w - mm[3]) * ii[3];
        o2.x = __expf(v2.x - mm[0]) * ii[0];  o2.y = __expf(v2.y - mm[1]) * ii[1];
        o2.z = __expf(v2.z - mm[2]) * ii[2];  o2.w = __expf(v2.w - mm[3]) * ii[3];
        *reinterpret_cast<float4*>(&probs[(size_t)r * CC + cb]) = o1;
        *reinterpret_cast<float4*>(&probs[(size_t)(r + 8) * CC + cb]) = o2;
    }
    if (r < hi) {
        float4 v1 = *reinterpret_cast<const float4*>(&logits[(size_t)r * CC + cb]);
        float4 o1;
        o1.x = __expf(v1.x - mm[0]) * ii[0];  o1.y = __expf(v1.y - mm[1]) * ii[1];
        o1.z = __expf(v1.z - mm[2]) * ii[2];  o1.w = __expf(v1.w - mm[3]) * ii[3];
        *reinterpret_cast<float4*>(&probs[(size_t)r * CC + cb]) = o1;
    }
}

// ===========================================================================
// Launch
// ===========================================================================
extern "C" void kernel_launch(void* const* d_in, const int* in_sizes, int n_in,
                              void* d_out, int out_size)
{
    const float* H  = nullptr;
    const int*   batch = nullptr;
    const float* W1 = nullptr;
    const float* b1 = nullptr;
    const float* W2 = nullptr;
    const float* b2 = nullptr;

    for (int i = 0; i < n_in; i++) {
        switch (in_sizes[i]) {
            case 128000000: H     = (const float*)d_in[i]; break;
            case 500000:    batch = (const int*)d_in[i];   break;
            case 65536:     W1    = (const float*)d_in[i]; break;
            case 256:       b1    = (const float*)d_in[i]; break;
            case 32768:     W2    = (const float*)d_in[i]; break;
            case 128:       b2    = (const float*)d_in[i]; break;
            default: break;
        }
    }

    float* out    = (float*)d_out;
    float* logits = out;
    float* probs  = out + (size_t)NN * CC;

    void *h16, *w1hi, *w2hi, *w2lo;
    cudaGetSymbolAddress(&h16, g_h16);
    cudaGetSymbolAddress(&w1hi, g_w1hi);
    cudaGetSymbolAddress(&w2hi, g_w2hi);
    cudaGetSymbolAddress(&w2lo, g_w2lo);

    cudaFuncSetAttribute(gemm_hmma<1, 1, 0>,
                         cudaFuncAttributeMaxDynamicSharedMemorySize, SMEM_BYTES);
    cudaFuncSetAttribute(gemm_hmma<0, 0, 1>,
                         cudaFuncAttributeMaxDynamicSharedMemorySize, SMEM_BYTES);

    // Pre-split weights (fp32 -> fp16 hi/lo, [n][kp])
    convert_w<<<192, 256>>>(W1, W2);

    const int mblocks = (NN + BM - 1) / BM;    // 3907

    // Layer 1: h = relu(H @ W1 + b1); fp32 A staged + fused cvt; single product
    dim3 g1(DD / BN, mblocks);                 // 2 x 3907 (A-tile pairs adjacent)
    gemm_hmma<1, 1, 0><<<g1, 256, SMEM_BYTES>>>(
        H, nullptr, (const uint32_t*)w1hi, nullptr,
        b1, nullptr, (uint32_t*)h16, NN, DD, 1);

    // Layer 2: logits = h @ W2 + b2; fp16 A via LDSM; 2-product (W2 split)
    dim3 g2(CC / BN, mblocks);                 // 1 x 3907
    gemm_hmma<0, 0, 1><<<g2, 256, SMEM_BYTES>>>(
        nullptr, (const uint32_t*)h16, (const uint32_t*)w2hi, (const uint32_t*)w2lo,
        b2, logits, nullptr, NN, CC, 0);

    // Segment softmax -> probs
    seg_softmax<<<SSEG, 256>>>(logits, batch, probs);
}